// round 1
// baseline (speedup 1.0000x reference)
#include <cuda_runtime.h>
#include <math.h>

#define BB 128
#define PP 196
#define EE 256
#define AA 256
#define DD 512
#define MM 512
#define VV 10000
#define LL 26
#define TT 25
#define GG 2048
#define XKC 768

// ---------------- device scratch (no allocs allowed) ----------------
__device__ float g_mean[BB * EE];
__device__ float g_h[BB * DD];
__device__ float g_c[BB * DD];
__device__ float g_att1[BB * PP * AA];        // enc@We.T + be   (25.7 MB)
__device__ float g_emb[TT * BB * MM];         // gathered embeddings, row r=t*B+b
__device__ float g_epre[TT * BB * GG];        // emb@Wih[:,:512].T + bih + bhh
__device__ float g_hall[TT * BB * DD];        // h_new per step (pred input)
__device__ float g_hg[4 * BB * 512];          // split-K partials of [att2|gatepre]
__device__ float g_xh[BB * XKC];              // [ctx(256) | h(512)]
__device__ float g_gates[2 * BB * GG];        // split-K partials of gates
__device__ float g_Wcat[512 * DD];            // rows: Wd(256) then Wfb(256)
__device__ float g_Wg[GG * XKC];              // cols: Wih[:,512:768] | Whh
__device__ float g_bias2[GG];                 // bih + bhh

// ---------------- setup kernels ----------------
__global__ void mean_kernel(const float* __restrict__ enc) {
    int b = blockIdx.x, e = threadIdx.x;
    const float* base = enc + (size_t)b * PP * EE + e;
    float s = 0.f;
    #pragma unroll 4
    for (int p = 0; p < PP; p++) s += base[(size_t)p * EE];
    g_mean[b * EE + e] = s * (1.0f / PP);
}

__global__ void prep_weights(const float* __restrict__ Wd, const float* __restrict__ Wfb,
                             const float* __restrict__ Wih, const float* __restrict__ Whh,
                             const float* __restrict__ bih, const float* __restrict__ bhh) {
    int i = blockIdx.x * blockDim.x + threadIdx.x;
    int stride = gridDim.x * blockDim.x;
    for (int idx = i; idx < 512 * DD; idx += stride) {
        int r = idx / DD, k = idx % DD;
        g_Wcat[idx] = (r < 256) ? Wd[r * DD + k] : Wfb[(r - 256) * DD + k];
    }
    for (int idx = i; idx < GG * XKC; idx += stride) {
        int j = idx / XKC, c = idx % XKC;
        g_Wg[idx] = (c < 256) ? Wih[j * XKC + 512 + c] : Whh[j * DD + (c - 256)];
    }
    for (int idx = i; idx < GG; idx += stride) g_bias2[idx] = bih[idx] + bhh[idx];
}

__global__ void gather_emb(const int* __restrict__ captions, const float* __restrict__ embW) {
    int r = blockIdx.x;              // r = t*B + b
    int t = r >> 7, b = r & 127;
    int tok = captions[b * LL + t];
    const float4* src = (const float4*)(embW + (size_t)tok * MM);
    float4* dst = (float4*)(g_emb + (size_t)r * MM);
    dst[threadIdx.x] = src[threadIdx.x];   // 128 threads * float4 = 512 floats
}

// ---------------- generic 128x128 SGEMM: C = A @ W^T (+bias) ----------------
__global__ __launch_bounds__(256) void sgemm128(
    int N, int K,
    const float* __restrict__ Amat, int lda,
    const float* __restrict__ Wmat, int ldw,
    const float* __restrict__ bias,
    float* __restrict__ Cout) {
    const int bx = blockIdx.x, by = blockIdx.y;
    __shared__ float As[8][128];
    __shared__ float Ws[8][128];
    const int tid = threadIdx.x;
    const int lRow = tid >> 1;
    const int lCol = (tid & 1) << 2;
    const float* Aptr = Amat + (size_t)(by * 128 + lRow) * lda + lCol;
    const float* Wptr = Wmat + (size_t)(bx * 128 + lRow) * ldw + lCol;
    const int trow = tid >> 4, tcol = tid & 15;
    float acc[8][8] = {};
    for (int k0 = 0; k0 < K; k0 += 8) {
        float4 av = *(const float4*)(Aptr + k0);
        float4 wv = *(const float4*)(Wptr + k0);
        As[lCol + 0][lRow] = av.x; As[lCol + 1][lRow] = av.y;
        As[lCol + 2][lRow] = av.z; As[lCol + 3][lRow] = av.w;
        Ws[lCol + 0][lRow] = wv.x; Ws[lCol + 1][lRow] = wv.y;
        Ws[lCol + 2][lRow] = wv.z; Ws[lCol + 3][lRow] = wv.w;
        __syncthreads();
        #pragma unroll
        for (int k = 0; k < 8; k++) {
            float a[8], w[8];
            *(float4*)(a)     = *(const float4*)&As[k][trow * 8];
            *(float4*)(a + 4) = *(const float4*)&As[k][trow * 8 + 4];
            *(float4*)(w)     = *(const float4*)&Ws[k][tcol * 8];
            *(float4*)(w + 4) = *(const float4*)&Ws[k][tcol * 8 + 4];
            #pragma unroll
            for (int i = 0; i < 8; i++)
                #pragma unroll
                for (int j = 0; j < 8; j++)
                    acc[i][j] += a[i] * w[j];
        }
        __syncthreads();
    }
    #pragma unroll
    for (int i = 0; i < 8; i++) {
        int m = by * 128 + trow * 8 + i;
        #pragma unroll
        for (int j4 = 0; j4 < 8; j4 += 4) {
            int n = bx * 128 + tcol * 8 + j4;
            float4 v = make_float4(acc[i][j4], acc[i][j4 + 1], acc[i][j4 + 2], acc[i][j4 + 3]);
            if (bias) { v.x += bias[n]; v.y += bias[n + 1]; v.z += bias[n + 2]; v.w += bias[n + 3]; }
            *(float4*)(Cout + (size_t)m * N + n) = v;
        }
    }
}

// ---------------- skinny SGEMM: M=128 fixed, 128x32 tiles, split-K slabs ----------------
__global__ __launch_bounds__(128) void sgemm_skinny(
    int N, int kLen,
    const float* __restrict__ Amat, int lda,
    const float* __restrict__ Wmat, int ldw,
    const float* __restrict__ bias,
    float* __restrict__ Cout) {
    const int bx = blockIdx.x;
    const int ks = blockIdx.y;
    const int kOff = ks * kLen;
    float* outp = Cout + (size_t)ks * 128 * N;
    __shared__ float As[32][132];
    __shared__ float Ws[32][36];
    const int tid = threadIdx.x;
    const int trow = tid >> 3;     // 0..15 -> rows trow*8..+7
    const int tcol = tid & 7;      // 0..7  -> cols tcol*4..+3
    float acc[8][4] = {};
    for (int k0 = 0; k0 < kLen; k0 += 32) {
        #pragma unroll
        for (int i = 0; i < 8; i++) {
            int idx = tid + i * 128;            // 0..1023
            int r = idx >> 3;
            int c4 = (idx & 7) << 2;
            float4 v = *(const float4*)(Amat + (size_t)r * lda + kOff + k0 + c4);
            As[c4 + 0][r] = v.x; As[c4 + 1][r] = v.y; As[c4 + 2][r] = v.z; As[c4 + 3][r] = v.w;
        }
        #pragma unroll
        for (int i = 0; i < 2; i++) {
            int idx = tid + i * 128;            // 0..255
            int r = idx >> 3;                   // 0..31 local n
            int c4 = (idx & 7) << 2;
            float4 v = *(const float4*)(Wmat + (size_t)(bx * 32 + r) * ldw + kOff + k0 + c4);
            Ws[c4 + 0][r] = v.x; Ws[c4 + 1][r] = v.y; Ws[c4 + 2][r] = v.z; Ws[c4 + 3][r] = v.w;
        }
        __syncthreads();
        #pragma unroll
        for (int k = 0; k < 32; k++) {
            float a[8];
            *(float4*)(a)     = *(const float4*)&As[k][trow * 8];
            *(float4*)(a + 4) = *(const float4*)&As[k][trow * 8 + 4];
            float4 w = *(const float4*)&Ws[k][tcol * 4];
            #pragma unroll
            for (int i = 0; i < 8; i++) {
                acc[i][0] += a[i] * w.x;
                acc[i][1] += a[i] * w.y;
                acc[i][2] += a[i] * w.z;
                acc[i][3] += a[i] * w.w;
            }
        }
        __syncthreads();
    }
    #pragma unroll
    for (int i = 0; i < 8; i++) {
        int m = trow * 8 + i;
        int n = bx * 32 + tcol * 4;
        float4 v = make_float4(acc[i][0], acc[i][1], acc[i][2], acc[i][3]);
        if (bias) { v.x += bias[n]; v.y += bias[n + 1]; v.z += bias[n + 2]; v.w += bias[n + 3]; }
        *(float4*)(outp + (size_t)m * N + n) = v;
    }
}

// ---------------- per-step attention (1 block per batch row) ----------------
__global__ __launch_bounds__(256) void attn_step(
    int t,
    const float* __restrict__ enc, const int* __restrict__ lengths,
    const float* __restrict__ bd, const float* __restrict__ bfb,
    const float* __restrict__ wf, const float* __restrict__ bfp,
    float* __restrict__ alpha_out) {
    const int b = blockIdx.x, tid = threadIdx.x;
    __shared__ float att2s[256], gs[256], wfs[256];
    __shared__ float sc[200];
    __shared__ float red[256];
    {
        float v = bd[tid], g = bfb[tid];
        #pragma unroll
        for (int s = 0; s < 4; s++) {
            v += g_hg[s * BB * 512 + b * 512 + tid];
            g += g_hg[s * BB * 512 + b * 512 + 256 + tid];
        }
        att2s[tid] = v; gs[tid] = g; wfs[tid] = wf[tid];
    }
    __syncthreads();
    float score = -3.0e38f;
    if (tid < PP) {
        const float4* arow = (const float4*)(g_att1 + ((size_t)b * PP + tid) * AA);
        float s0 = 0, s1 = 0, s2 = 0, s3 = 0;
        #pragma unroll 8
        for (int a4 = 0; a4 < AA / 4; a4++) {
            float4 av = arow[a4];
            int a = a4 * 4;
            s0 += fmaxf(av.x + att2s[a + 0], 0.f) * wfs[a + 0];
            s1 += fmaxf(av.y + att2s[a + 1], 0.f) * wfs[a + 1];
            s2 += fmaxf(av.z + att2s[a + 2], 0.f) * wfs[a + 2];
            s3 += fmaxf(av.w + att2s[a + 3], 0.f) * wfs[a + 3];
        }
        score = s0 + s1 + s2 + s3 + bfp[0];
    }
    red[tid] = score;
    __syncthreads();
    for (int off = 128; off > 0; off >>= 1) {
        if (tid < off) red[tid] = fmaxf(red[tid], red[tid + off]);
        __syncthreads();
    }
    float mx = red[0];
    __syncthreads();
    float e = 0.f;
    if (tid < PP) e = expf(score - mx);
    red[tid] = e;
    __syncthreads();
    for (int off = 128; off > 0; off >>= 1) {
        if (tid < off) red[tid] += red[tid + off];
        __syncthreads();
    }
    float inv = 1.f / red[0];
    __syncthreads();
    const int active = t < (lengths[b] - 1);
    if (tid < PP) {
        float al = e * inv;
        sc[tid] = al;
        alpha_out[((size_t)b * TT + t) * PP + tid] = active ? al : 0.f;
    }
    __syncthreads();
    // ctx[e] = sum_p alpha[p] * enc[b,p,e]
    const float* eb = enc + (size_t)b * PP * EE + tid;
    float c0 = 0, c1 = 0, c2 = 0, c3 = 0;
    for (int p = 0; p < PP; p += 4) {
        c0 += sc[p]     * eb[(size_t)(p)     * EE];
        c1 += sc[p + 1] * eb[(size_t)(p + 1) * EE];
        c2 += sc[p + 2] * eb[(size_t)(p + 2) * EE];
        c3 += sc[p + 3] * eb[(size_t)(p + 3) * EE];
    }
    float ctx = c0 + c1 + c2 + c3;
    float gate = 1.f / (1.f + expf(-gs[tid]));
    ctx *= gate;
    g_xh[b * XKC + tid] = ctx;
    g_xh[b * XKC + 256 + tid] = g_h[b * DD + tid];
    g_xh[b * XKC + 512 + tid] = g_h[b * DD + 256 + tid];
}

// ---------------- per-step LSTM pointwise ----------------
__global__ __launch_bounds__(512) void lstm_pointwise(int t, const int* __restrict__ lengths) {
    const int b = blockIdx.x, d = threadIdx.x;
    const int rb = b * GG;
    float gv[4];
    #pragma unroll
    for (int q = 0; q < 4; q++) {
        int j = q * DD + d;
        gv[q] = g_epre[((size_t)t * BB + b) * GG + j] + g_gates[rb + j] + g_gates[BB * GG + rb + j];
    }
    float ig = 1.f / (1.f + expf(-gv[0]));
    float fg = 1.f / (1.f + expf(-gv[1]));
    float gg = tanhf(gv[2]);
    float og = 1.f / (1.f + expf(-gv[3]));
    float c = g_c[b * DD + d];
    float cn = fg * c + ig * gg;
    float hn = og * tanhf(cn);
    g_hall[((size_t)t * BB + b) * DD + d] = hn;
    if (t < lengths[b] - 1) {
        g_h[b * DD + d] = hn;
        g_c[b * DD + d] = cn;
    }
}

// ---------------- final masked vocab GEMM: preds = hall @ Wfc^T + bfc ----------------
__global__ __launch_bounds__(256) void final_pred(
    const float* __restrict__ Wfc, const float* __restrict__ bfc,
    const int* __restrict__ lengths,
    float* __restrict__ out) {
    const int bx = blockIdx.x, t = blockIdx.y;
    __shared__ float As[8][128];
    __shared__ float Ws[8][128];
    const int tid = threadIdx.x;
    const int lRow = tid >> 1;
    const int lCol = (tid & 1) << 2;
    const float* Aptr = g_hall + ((size_t)t * 128 + lRow) * DD + lCol;
    const int wRow = bx * 128 + lRow;
    const bool wok = wRow < VV;
    const float* Wptr = Wfc + (size_t)(wok ? wRow : 0) * DD + lCol;
    const int trow = tid >> 4, tcol = tid & 15;
    float acc[8][8] = {};
    for (int k0 = 0; k0 < DD; k0 += 8) {
        float4 av = *(const float4*)(Aptr + k0);
        float4 wv = wok ? *(const float4*)(Wptr + k0) : make_float4(0.f, 0.f, 0.f, 0.f);
        As[lCol + 0][lRow] = av.x; As[lCol + 1][lRow] = av.y;
        As[lCol + 2][lRow] = av.z; As[lCol + 3][lRow] = av.w;
        Ws[lCol + 0][lRow] = wv.x; Ws[lCol + 1][lRow] = wv.y;
        Ws[lCol + 2][lRow] = wv.z; Ws[lCol + 3][lRow] = wv.w;
        __syncthreads();
        #pragma unroll
        for (int k = 0; k < 8; k++) {
            float a[8], w[8];
            *(float4*)(a)     = *(const float4*)&As[k][trow * 8];
            *(float4*)(a + 4) = *(const float4*)&As[k][trow * 8 + 4];
            *(float4*)(w)     = *(const float4*)&Ws[k][tcol * 8];
            *(float4*)(w + 4) = *(const float4*)&Ws[k][tcol * 8 + 4];
            #pragma unroll
            for (int i = 0; i < 8; i++)
                #pragma unroll
                for (int j = 0; j < 8; j++)
                    acc[i][j] += a[i] * w[j];
        }
        __syncthreads();
    }
    #pragma unroll
    for (int i = 0; i < 8; i++) {
        int b = trow * 8 + i;
        bool active = t < (lengths[b] - 1);
        float* orow = out + (size_t)b * TT * VV + (size_t)t * VV;
        #pragma unroll
        for (int j4 = 0; j4 < 8; j4 += 4) {
            int n = bx * 128 + tcol * 8 + j4;
            if (n < VV) {
                float4 v;
                if (active)
                    v = make_float4(acc[i][j4] + bfc[n], acc[i][j4 + 1] + bfc[n + 1],
                                    acc[i][j4 + 2] + bfc[n + 2], acc[i][j4 + 3] + bfc[n + 3]);
                else
                    v = make_float4(0.f, 0.f, 0.f, 0.f);
                *(float4*)(orow + n) = v;
            }
        }
    }
}

// ---------------- launch ----------------
extern "C" void kernel_launch(void* const* d_in, const int* in_sizes, int n_in,
                              void* d_out, int out_size) {
    const float* enc      = (const float*)d_in[0];
    const int*   captions = (const int*)d_in[1];
    const int*   lengths  = (const int*)d_in[2];
    const float* embW     = (const float*)d_in[3];
    const float* We       = (const float*)d_in[4];
    const float* be       = (const float*)d_in[5];
    const float* Wd       = (const float*)d_in[6];
    const float* bd       = (const float*)d_in[7];
    const float* wf       = (const float*)d_in[8];
    const float* bfp      = (const float*)d_in[9];
    const float* Wih      = (const float*)d_in[10];
    const float* bih      = (const float*)d_in[11];
    const float* Whh      = (const float*)d_in[12];
    const float* bhh      = (const float*)d_in[13];
    const float* Wh0      = (const float*)d_in[14];
    const float* bh0      = (const float*)d_in[15];
    const float* Wc0      = (const float*)d_in[16];
    const float* bc0      = (const float*)d_in[17];
    const float* Wfb      = (const float*)d_in[18];
    const float* bfb      = (const float*)d_in[19];
    const float* Wfc      = (const float*)d_in[20];
    const float* bfc      = (const float*)d_in[21];
    float* out = (float*)d_out;
    float* alpha_out = out + (size_t)BB * TT * VV;

    float *p_mean, *p_h, *p_c, *p_att1, *p_emb, *p_epre, *p_hg, *p_xh, *p_gates, *p_Wcat, *p_Wg, *p_bias2;
    cudaGetSymbolAddress((void**)&p_mean,  g_mean);
    cudaGetSymbolAddress((void**)&p_h,     g_h);
    cudaGetSymbolAddress((void**)&p_c,     g_c);
    cudaGetSymbolAddress((void**)&p_att1,  g_att1);
    cudaGetSymbolAddress((void**)&p_emb,   g_emb);
    cudaGetSymbolAddress((void**)&p_epre,  g_epre);
    cudaGetSymbolAddress((void**)&p_hg,    g_hg);
    cudaGetSymbolAddress((void**)&p_xh,    g_xh);
    cudaGetSymbolAddress((void**)&p_gates, g_gates);
    cudaGetSymbolAddress((void**)&p_Wcat,  g_Wcat);
    cudaGetSymbolAddress((void**)&p_Wg,    g_Wg);
    cudaGetSymbolAddress((void**)&p_bias2, g_bias2);

    // ---- setup (loop-invariant) ----
    mean_kernel<<<BB, EE>>>(enc);
    prep_weights<<<1024, 256>>>(Wd, Wfb, Wih, Whh, bih, bhh);
    gather_emb<<<TT * BB, 128>>>(captions, embW);
    // h0 = mean @ Wh0^T + bh0 ; c0 likewise   (M=128, N=512, K=256)
    sgemm_skinny<<<dim3(512 / 32, 1), 128>>>(512, 256, p_mean, EE, Wh0, EE, bh0, p_h);
    sgemm_skinny<<<dim3(512 / 32, 1), 128>>>(512, 256, p_mean, EE, Wc0, EE, bc0, p_c);
    // att1 = enc @ We^T + be   (M=25088, N=256, K=256)
    sgemm128<<<dim3(AA / 128, BB * PP / 128), 256>>>(AA, EE, enc, EE, We, EE, be, p_att1);
    // epre = emb @ Wih[:, :512]^T + (bih+bhh)   (M=3200, N=2048, K=512)
    sgemm128<<<dim3(GG / 128, TT * BB / 128), 256>>>(GG, MM, p_emb, MM, Wih, XKC, p_bias2, p_epre);

    // ---- recurrence ----
    for (int t = 0; t < TT; t++) {
        // [att2 | gatepre] = h @ [Wd;Wfb]^T   (split-K 4, partials summed in attn_step)
        sgemm_skinny<<<dim3(512 / 32, 4), 128>>>(512, 128, p_h, DD, p_Wcat, DD, nullptr, p_hg);
        attn_step<<<BB, 256>>>(t, enc, lengths, bd, bfb, wf, bfp, alpha_out);
        // gates partial = [ctx|h] @ [Wih_ctx|Whh]^T   (split-K 2, summed in pointwise)
        sgemm_skinny<<<dim3(GG / 32, 2), 128>>>(GG, 384, p_xh, XKC, p_Wg, XKC, nullptr, p_gates);
        lstm_pointwise<<<BB, 512>>>(t, lengths);
    }

    // ---- vocab head, masked ----
    final_pred<<<dim3((VV + 127) / 128, TT), 256>>>(Wfc, bfc, lengths, out);
}